// round 9
// baseline (speedup 1.0000x reference)
#include <cuda_runtime.h>
#include <cuda_fp16.h>
#include <math.h>
#include <stdint.h>

// Problem constants
#define BB 256
#define NN 50
#define FF 6144
#define HH 4
#define OO 64
#define NT (HH*OO)          // 256
#define MT (BB*NN)          // 12800

// GEMM tiling: CTA tile 64 x 256, 2 CTAs/SM, fp16 MMA, fp32 A in smem
#define BM 64
#define BN 256
#define BK 32
#define RSA 40                          // A row stride (floats)
#define RSB 40                          // B row stride (halves), LDSM-safe
#define NSTG 3
#define A_ST_BYTES (BM * RSA * 4)       // 10240
#define B_ST_BYTES (BN * RSB * 2)       // 20480
#define SMEM_BYTES (NSTG * (A_ST_BYTES + B_ST_BYTES))   // 92160
#define NTILES (MT/BM)                  // 200
#define KUNITS (FF/BK)                  // 192
#define UNITS_TOTAL (NTILES * KUNITS)   // 38400
#define GRID_G 296
#define NTHREADS 256

__device__ float  g_Wh[(size_t)MT * NT];              // 13.1 MB, zeroed per launch
__device__ __half g_Bth[(size_t)NT * FF];             // 3.1 MB fp16 B, K-major
__device__ unsigned char g_adj[(size_t)BB * NN * NN]; // 640 KB

__device__ __forceinline__ uint32_t smem_u32(const void* p) {
    uint32_t a;
    asm("{ .reg .u64 t; cvta.to.shared.u64 t, %1; cvt.u32.u64 %0, t; }" : "=r"(a) : "l"(p));
    return a;
}
__device__ __forceinline__ unsigned packh2(float x, float y) {
    half2 h = __floats2half2_rn(x, y);
    return *(unsigned*)&h;
}
__device__ __forceinline__ void mma_f16(float c[4],
                                        const unsigned a[4],
                                        const unsigned b[2]) {
    asm volatile(
        "mma.sync.aligned.m16n8k16.row.col.f32.f16.f16.f32 "
        "{%0,%1,%2,%3}, {%4,%5,%6,%7}, {%8,%9}, {%0,%1,%2,%3};"
        : "+f"(c[0]), "+f"(c[1]), "+f"(c[2]), "+f"(c[3])
        : "r"(a[0]), "r"(a[1]), "r"(a[2]), "r"(a[3]),
          "r"(b[0]), "r"(b[1]));
}
#define CP16(dst, src) \
    asm volatile("cp.async.cg.shared.global [%0], [%1], 16;" :: "r"(dst), "l"(src))
#define CP_COMMIT() asm volatile("cp.async.commit_group;" ::: "memory")
#define CP_WAIT1()  asm volatile("cp.async.wait_group 1;"  ::: "memory")

// ---------------------------------------------------------------------------
__global__ void zero_kernel()
{
    size_t i = (size_t)blockIdx.x * blockDim.x + threadIdx.x;
    float4* p = (float4*)g_Wh;
    size_t n4 = (size_t)MT * NT / 4;
    for (; i < n4; i += (size_t)gridDim.x * blockDim.x)
        p[i] = make_float4(0.f, 0.f, 0.f, 0.f);
}

// ---------------------------------------------------------------------------
__global__ __launch_bounds__(256)
void adj_kernel(const float* __restrict__ probs, const float* __restrict__ u)
{
    int idx = blockIdx.x * 256 + threadIdx.x;
    if (idx >= BB * NN * NN) return;
    float p = probs[idx];
    float2 uv = *(const float2*)&u[(size_t)idx * 2];
    float x0 = p, x1 = 1.f - p;
    float mx = fmaxf(x0, x1);
    float e0 = __expf(x0 - mx), e1 = __expf(x1 - mx);
    float inv = 1.f / (e0 + e1);
    float l0 = __logf(e0 * inv + 1e-5f);
    float l1 = __logf(e1 * inv + 1e-5f);
    float g0 = -__logf(-__logf(uv.x + 1e-10f) + 1e-10f);
    float g1 = -__logf(-__logf(uv.y + 1e-10f) + 1e-10f);
    g_adj[idx] = (l0 + g0 >= l1 + g1) ? 1 : 0;
}

// ---------------------------------------------------------------------------
// W (H,F,O) fp32 -> g_Bth[n=h*64+o][k=f] fp16 (transpose + convert)
// ---------------------------------------------------------------------------
__global__ __launch_bounds__(256)
void wT_kernel(const float* __restrict__ W)
{
    __shared__ float t[32][65];
    const int f0 = blockIdx.x * 32;
    const int h  = blockIdx.y;
    for (int i = threadIdx.x; i < 32 * 64; i += 256) {
        int fi = i >> 6, o = i & 63;
        t[fi][o] = W[((size_t)h * FF + f0 + fi) * OO + o];
    }
    __syncthreads();
    for (int i = threadIdx.x; i < 32 * 64; i += 256) {
        int o = i >> 5, fi = i & 31;
        g_Bth[(size_t)(h * 64 + o) * FF + f0 + fi] = __float2half_rn(t[fi][o]);
    }
}

// ---------------------------------------------------------------------------
// Kernel A: persistent fp16 GEMM, 64x256 tile, 2 CTAs/SM, cp.async 3-stage.
// ---------------------------------------------------------------------------
__global__ __launch_bounds__(NTHREADS, 2)
void gemm_f16(const float* __restrict__ hmat)
{
    extern __shared__ char smraw[];
    float*  Asm = (float*)smraw;
    __half* Bsm = (__half*)(smraw + NSTG * A_ST_BYTES);
    const uint32_t aB = smem_u32(Asm);
    const uint32_t bB = smem_u32(Bsm);

    const int tid  = threadIdx.x;
    const int lane = tid & 31;
    const int wid  = tid >> 5;
    const int wm   = wid & 1;              // 2 x 32 m
    const int wn   = wid >> 1;             // 4 x 64 n

    const int c  = blockIdx.x;
    int u        = (int)(((long long)UNITS_TOTAL * c) / GRID_G);
    const int u1 = (int)(((long long)UNITS_TOTAL * (c + 1)) / GRID_G);

    // A tile: 64m x 32k floats = 512 float4;  p -> m = p>>3, kq = (p&7)*4
    // B tile: 256n x 32k halves = 1024 int4;  p -> n = p>>2, k8 = (p&3)*8
#define ISSUE(Abase, kt, slot)                                                \
    {                                                                         \
        const int k0 = (kt) * BK;                                             \
        _Pragma("unroll")                                                     \
        for (int i = 0; i < 2; i++) {                                         \
            int p = tid + i * NTHREADS;                                       \
            int m = p >> 3, kq = (p & 7) * 4;                                 \
            CP16(aB + (slot) * A_ST_BYTES + (m * RSA + kq) * 4,               \
                 (Abase) + (size_t)m * FF + k0 + kq);                         \
        }                                                                     \
        _Pragma("unroll")                                                     \
        for (int i = 0; i < 4; i++) {                                         \
            int p = tid + i * NTHREADS;                                       \
            int n = p >> 2, k8 = (p & 3) * 8;                                 \
            CP16(bB + (slot) * B_ST_BYTES + (n * RSB + k8) * 2,               \
                 g_Bth + (size_t)n * FF + k0 + k8);                           \
        }                                                                     \
    }

    while (u < u1) {
        const int tile = u / KUNITS;
        const int kbeg = u - tile * KUNITS;
        const int seg  = min(KUNITS - kbeg, u1 - u);
        const int kend = kbeg + seg;
        const int row0 = tile * BM;
        const float* Abase = hmat + (size_t)row0 * FF;

        // prologue: 2 stages in flight
#pragma unroll
        for (int s = 0; s < 2; s++) {
            if (s < seg) ISSUE(Abase, kbeg + s, s);
            CP_COMMIT();
        }

        float acc[2][8][4];
#pragma unroll
        for (int i = 0; i < 2; i++)
#pragma unroll
            for (int j = 0; j < 8; j++)
#pragma unroll
                for (int q = 0; q < 4; q++) acc[i][j][q] = 0.f;

        int slot = 0;
        for (int kt = kbeg; kt < kend; kt++) {
            CP_WAIT1();
            __syncthreads();
            if (kt + 2 < kend) {
                int s2 = slot + 2; if (s2 >= NSTG) s2 -= NSTG;
                ISSUE(Abase, kt + 2, s2);
            }
            CP_COMMIT();

            const float*   Ab = Asm + slot * (BM * RSA);
            const uint32_t bS = bB + slot * B_ST_BYTES;
            const int mA = wm * 32 + (lane >> 2);
            const int r2 = (lane & 3) * 2;
            const int j8 = lane & 7;
            const int mi = lane >> 3;

#pragma unroll
            for (int ks = 0; ks < 2; ks++) {
                const int kb = ks * 16;
                unsigned a[2][4], b[8][2];
#pragma unroll
                for (int mt = 0; mt < 2; mt++) {
                    const int m = mA + mt * 16;
                    float2 f;
                    f = *(const float2*)(Ab + m * RSA + kb + r2);
                    a[mt][0] = packh2(f.x, f.y);
                    f = *(const float2*)(Ab + (m + 8) * RSA + kb + r2);
                    a[mt][1] = packh2(f.x, f.y);
                    f = *(const float2*)(Ab + m * RSA + kb + 8 + r2);
                    a[mt][2] = packh2(f.x, f.y);
                    f = *(const float2*)(Ab + (m + 8) * RSA + kb + 8 + r2);
                    a[mt][3] = packh2(f.x, f.y);
                }
#pragma unroll
                for (int pr = 0; pr < 4; pr++) {
                    const int n8 = wn * 64 + pr * 16;
                    uint32_t ad = bS +
                        ((n8 + (mi >> 1) * 8 + j8) * RSB + kb + (mi & 1) * 8) * 2;
                    asm volatile(
                        "ldmatrix.sync.aligned.m8n8.x4.shared.b16 {%0,%1,%2,%3}, [%4];"
                        : "=r"(b[2 * pr][0]), "=r"(b[2 * pr][1]),
                          "=r"(b[2 * pr + 1][0]), "=r"(b[2 * pr + 1][1])
                        : "r"(ad));
                }
#pragma unroll
                for (int mt = 0; mt < 2; mt++)
#pragma unroll
                    for (int nt = 0; nt < 8; nt++)
                        mma_f16(acc[mt][nt], a[mt], b[nt]);
            }

            if (++slot == NSTG) slot = 0;
        }
        __syncthreads();   // protect slots before next segment's prologue

        // flush tile segment via atomicAdd
#pragma unroll
        for (int mt = 0; mt < 2; mt++) {
            int r = row0 + wm * 32 + mt * 16 + (lane >> 2);
#pragma unroll
            for (int nt = 0; nt < 8; nt++) {
                int cc = wn * 64 + nt * 8 + (lane & 3) * 2;
                atomicAdd(&g_Wh[(size_t)r * NT + cc],           acc[mt][nt][0]);
                atomicAdd(&g_Wh[(size_t)r * NT + cc + 1],       acc[mt][nt][1]);
                atomicAdd(&g_Wh[(size_t)(r + 8) * NT + cc],     acc[mt][nt][2]);
                atomicAdd(&g_Wh[(size_t)(r + 8) * NT + cc + 1], acc[mt][nt][3]);
            }
        }

        u += seg;
    }
#undef ISSUE
}

// ---------------------------------------------------------------------------
// Kernel B: GAT attention + ELU. grid (256,4), 256 threads, 5 blocks/SM.
// ---------------------------------------------------------------------------
#define NP 52
__global__ __launch_bounds__(256, 5)
void attn_kernel(const float* __restrict__ a, float* __restrict__ out)
{
    __shared__ float sWh[NP][68];
    __shared__ float sA2[NP][68];
    __shared__ float sE[NP][NP];
    __shared__ float sS1[NN];
    __shared__ unsigned char sAdj[NN * NN];

    const int b    = blockIdx.x;
    const int h    = blockIdx.y;
    const int tid  = threadIdx.x;
    const int lane = tid & 31;
    const int wid  = tid >> 5;

    {
        const unsigned* src = (const unsigned*)(g_adj + (size_t)b * NN * NN);
        unsigned* dst = (unsigned*)sAdj;
        for (int i = tid; i < NN * NN / 4; i += 256) dst[i] = src[i];
    }

    if (tid < 2 * 68) {
        int r = 50 + tid / 68, cidx = tid % 68;
        sWh[r][cidx] = 0.f;
        sA2[r][cidx] = 0.f;
    }

    for (int idx = tid; idx < NN * OO / 4; idx += 256) {
        int n_ = idx >> 4;
        int o4 = (idx & 15) * 4;
        float4 w  = *(const float4*)&g_Wh[(size_t)(b * NN + n_) * NT + h * OO + o4];
        float4 av = *(const float4*)&a[(size_t)(h * NN + n_) * (2 * OO) + OO + o4];
        *(float4*)&sWh[n_][o4] = w;
        *(float4*)&sA2[n_][o4] = av;
    }
    __syncthreads();

    for (int n_ = wid; n_ < NN; n_ += 8) {
        float a1v0 = a[(size_t)(h * NN + n_) * (2 * OO) + lane];
        float a1v1 = a[(size_t)(h * NN + n_) * (2 * OO) + lane + 32];
        float v = sWh[n_][lane] * a1v0 + sWh[n_][lane + 32] * a1v1;
#pragma unroll
        for (int off = 16; off; off >>= 1) v += __shfl_xor_sync(0xffffffffu, v, off);
        if (lane == 0) sS1[n_] = v;
    }

    if (tid < 169) {
        const int n0 = (tid / 13) * 4;
        const int m0 = (tid % 13) * 4;
        float acc[4][4];
#pragma unroll
        for (int i = 0; i < 4; i++)
#pragma unroll
            for (int j = 0; j < 4; j++) acc[i][j] = 0.f;
#pragma unroll 8
        for (int o = 0; o < OO; o++) {
            float av[4], wv[4];
#pragma unroll
            for (int i = 0; i < 4; i++) av[i] = sA2[n0 + i][o];
#pragma unroll
            for (int j = 0; j < 4; j++) wv[j] = sWh[m0 + j][o];
#pragma unroll
            for (int i = 0; i < 4; i++)
#pragma unroll
                for (int j = 0; j < 4; j++)
                    acc[i][j] = fmaf(av[i], wv[j], acc[i][j]);
        }
#pragma unroll
        for (int i = 0; i < 4; i++)
#pragma unroll
            for (int j = 0; j < 4; j++) sE[n0 + i][m0 + j] = acc[i][j];
    }
    __syncthreads();

    for (int n_ = wid; n_ < NN; n_ += 8) {
        float s1v = sS1[n_];
        int m0 = lane, m1 = lane + 32;
        float t0 = s1v + sE[n_][m0];
        t0 = (t0 >= 0.f) ? t0 : 0.2f * t0;
        float v0 = sAdj[n_ * NN + m0] ? t0 : -9e15f;
        float v1 = -9e15f;
        if (m1 < NN) {
            float t1 = s1v + sE[n_][m1];
            t1 = (t1 >= 0.f) ? t1 : 0.2f * t1;
            v1 = sAdj[n_ * NN + m1] ? t1 : -9e15f;
        }
        float mx = fmaxf(v0, v1);
#pragma unroll
        for (int off = 16; off; off >>= 1)
            mx = fmaxf(mx, __shfl_xor_sync(0xffffffffu, mx, off));
        float e0_ = __expf(v0 - mx);
        float e1_ = (m1 < NN) ? __expf(v1 - mx) : 0.f;
        float sum = e0_ + e1_;
#pragma unroll
        for (int off = 16; off; off >>= 1)
            sum += __shfl_xor_sync(0xffffffffu, sum, off);
        float inv = 1.f / sum;
        sE[n_][m0] = e0_ * inv;
        if (m1 < NN) sE[n_][m1] = e1_ * inv;
    }
    __syncthreads();

    if (tid < 208) {
        const int n0 = (tid / 16) * 4;
        const int o4 = (tid % 16) * 4;
        float4 acc[4];
#pragma unroll
        for (int i = 0; i < 4; i++) acc[i] = make_float4(0.f, 0.f, 0.f, 0.f);
#pragma unroll 5
        for (int m = 0; m < NN; m++) {
            float4 wv = *(const float4*)&sWh[m][o4];
#pragma unroll
            for (int i = 0; i < 4; i++) {
                float at = sE[n0 + i][m];
                acc[i].x = fmaf(at, wv.x, acc[i].x);
                acc[i].y = fmaf(at, wv.y, acc[i].y);
                acc[i].z = fmaf(at, wv.z, acc[i].z);
                acc[i].w = fmaf(at, wv.w, acc[i].w);
            }
        }
#pragma unroll
        for (int i = 0; i < 4; i++) {
            int n_ = n0 + i;
            if (n_ < NN) {
                float4 wv = *(const float4*)&sWh[n_][o4];
                float4 v = make_float4(acc[i].x + 0.3f * wv.x,
                                       acc[i].y + 0.3f * wv.y,
                                       acc[i].z + 0.3f * wv.z,
                                       acc[i].w + 0.3f * wv.w);
                v.x = (v.x > 0.f) ? v.x : expm1f(v.x);
                v.y = (v.y > 0.f) ? v.y : expm1f(v.y);
                v.z = (v.z > 0.f) ? v.z : expm1f(v.z);
                v.w = (v.w > 0.f) ? v.w : expm1f(v.w);
                *(float4*)&out[(size_t)(b * NN + n_) * NT + h * OO + o4] = v;
            }
        }
    }
}

// ---------------------------------------------------------------------------
extern "C" void kernel_launch(void* const* d_in, const int* in_sizes, int n_in,
                              void* d_out, int out_size)
{
    const float* h_    = (const float*)d_in[0];  // (B, N, F)
    const float* probs = (const float*)d_in[1];  // (B, N*N)
    const float* u_    = (const float*)d_in[2];  // (B, N*N, 2)
    const float* W_    = (const float*)d_in[3];  // (H, F, O)
    const float* a_    = (const float*)d_in[4];  // (H, N, 2*O)
    float* out = (float*)d_out;

    zero_kernel<<<592, 256>>>();
    adj_kernel<<<(BB * NN * NN + 255) / 256, 256>>>(probs, u_);

    dim3 tgrid(FF / 32, HH);
    wT_kernel<<<tgrid, 256>>>(W_);

    cudaFuncSetAttribute(gemm_f16, cudaFuncAttributeMaxDynamicSharedMemorySize,
                         SMEM_BYTES);
    gemm_f16<<<GRID_G, NTHREADS, SMEM_BYTES>>>(h_);

    dim3 agrid(BB, HH);
    attn_kernel<<<agrid, 256>>>(a_, out);
}

// round 10
// speedup vs baseline: 1.0957x; 1.0957x over previous
#include <cuda_runtime.h>
#include <cuda_fp16.h>
#include <math.h>
#include <stdint.h>

// Problem constants
#define BB 256
#define NN 50
#define FF 6144
#define HH 4
#define OO 64
#define NT (HH*OO)          // 256
#define MT (BB*NN)          // 12800

// GEMM tiling: CTA tile 128 x 256 (full width), fp16 smem both operands
#define BM 128
#define BN 256
#define BK 32
#define RSAH 40                         // A row stride (halves)
#define RSB 40                          // B row stride (halves)
#define NSTG 4
#define A_ST_BYTES (BM * RSAH * 2)      // 10240
#define B_ST_BYTES (BN * RSB  * 2)      // 20480
#define SMEM_BYTES (NSTG * (A_ST_BYTES + B_ST_BYTES))   // 122880
#define NTILES (MT/BM)                  // 100
#define KUNITS (FF/BK)                  // 192
#define UNITS_TOTAL (NTILES * KUNITS)   // 19200
#define GRID_G 148
#define NTHREADS 512

__device__ float  g_Wh[(size_t)MT * NT];              // 13.1 MB, zeroed per launch
__device__ __half g_Bth[(size_t)NT * FF];             // 3.1 MB fp16 B, K-major
__device__ unsigned char g_adj[(size_t)BB * NN * NN]; // 640 KB

__device__ __forceinline__ uint32_t smem_u32(const void* p) {
    uint32_t a;
    asm("{ .reg .u64 t; cvta.to.shared.u64 t, %1; cvt.u32.u64 %0, t; }" : "=r"(a) : "l"(p));
    return a;
}
__device__ __forceinline__ unsigned packh2(float x, float y) {
    half2 h = __floats2half2_rn(x, y);
    return *(unsigned*)&h;
}
__device__ __forceinline__ void mma_f16(float c[4],
                                        const unsigned a[4],
                                        const unsigned b[2]) {
    asm volatile(
        "mma.sync.aligned.m16n8k16.row.col.f32.f16.f16.f32 "
        "{%0,%1,%2,%3}, {%4,%5,%6,%7}, {%8,%9}, {%0,%1,%2,%3};"
        : "+f"(c[0]), "+f"(c[1]), "+f"(c[2]), "+f"(c[3])
        : "r"(a[0]), "r"(a[1]), "r"(a[2]), "r"(a[3]),
          "r"(b[0]), "r"(b[1]));
}
#define CP16(dst, src) \
    asm volatile("cp.async.cg.shared.global [%0], [%1], 16;" :: "r"(dst), "l"(src))
#define CP_COMMIT() asm volatile("cp.async.commit_group;" ::: "memory")
#define CP_WAIT2()  asm volatile("cp.async.wait_group 2;"  ::: "memory")

// ---------------------------------------------------------------------------
__global__ void zero_kernel()
{
    size_t i = (size_t)blockIdx.x * blockDim.x + threadIdx.x;
    float4* p = (float4*)g_Wh;
    size_t n4 = (size_t)MT * NT / 4;
    for (; i < n4; i += (size_t)gridDim.x * blockDim.x)
        p[i] = make_float4(0.f, 0.f, 0.f, 0.f);
}

// ---------------------------------------------------------------------------
__global__ __launch_bounds__(256)
void adj_kernel(const float* __restrict__ probs, const float* __restrict__ u)
{
    int idx = blockIdx.x * 256 + threadIdx.x;
    if (idx >= BB * NN * NN) return;
    float p = probs[idx];
    float2 uv = *(const float2*)&u[(size_t)idx * 2];
    float x0 = p, x1 = 1.f - p;
    float mx = fmaxf(x0, x1);
    float e0 = __expf(x0 - mx), e1 = __expf(x1 - mx);
    float inv = 1.f / (e0 + e1);
    float l0 = __logf(e0 * inv + 1e-5f);
    float l1 = __logf(e1 * inv + 1e-5f);
    float g0 = -__logf(-__logf(uv.x + 1e-10f) + 1e-10f);
    float g1 = -__logf(-__logf(uv.y + 1e-10f) + 1e-10f);
    g_adj[idx] = (l0 + g0 >= l1 + g1) ? 1 : 0;
}

// ---------------------------------------------------------------------------
// W (H,F,O) fp32 -> g_Bth[n=h*64+o][k=f] fp16 (transpose + convert)
// ---------------------------------------------------------------------------
__global__ __launch_bounds__(256)
void wT_kernel(const float* __restrict__ W)
{
    __shared__ float t[32][65];
    const int f0 = blockIdx.x * 32;
    const int h  = blockIdx.y;
    for (int i = threadIdx.x; i < 32 * 64; i += 256) {
        int fi = i >> 6, o = i & 63;
        t[fi][o] = W[((size_t)h * FF + f0 + fi) * OO + o];
    }
    __syncthreads();
    for (int i = threadIdx.x; i < 32 * 64; i += 256) {
        int o = i >> 5, fi = i & 31;
        g_Bth[(size_t)(h * 64 + o) * FF + f0 + fi] = __float2half_rn(t[fi][o]);
    }
}

// ---------------------------------------------------------------------------
// Kernel A: persistent fp16 GEMM. A: LDG+cvt+STS (fp16 smem, ldmatrix).
// B: cp.async 4-stage. All fragments via ldmatrix.x4.
// ---------------------------------------------------------------------------
__global__ __launch_bounds__(NTHREADS, 1)
void gemm_f16(const float* __restrict__ hmat)
{
    extern __shared__ char smraw[];
    __half* Ash = (__half*)smraw;                          // [NSTG][BM][RSAH]
    __half* Bsh = (__half*)(smraw + NSTG * A_ST_BYTES);    // [NSTG][BN][RSB]
    const uint32_t aB = smem_u32(Ash);
    const uint32_t bB = smem_u32(Bsh);

    const int tid  = threadIdx.x;
    const int lane = tid & 31;
    const int wid  = tid >> 5;
    const int wm   = wid & 3;              // 4 x 32 m
    const int wn   = wid >> 2;             // 4 x 64 n

    const int c  = blockIdx.x;
    int u        = (int)(((long long)UNITS_TOTAL * c) / GRID_G);
    const int u1 = (int)(((long long)UNITS_TOTAL * (c + 1)) / GRID_G);

    float4 va[2];

    // A: 128m x 32k floats = 1024 float4; p -> m = p>>3, kq = (p&7)*4
    // B: 256n x 32k halves = 1024 int4;   p -> n = p>>2, k8 = (p&3)*8
#define LDG_A(Abase, kt)                                                      \
    {                                                                         \
        const int k0 = (kt) * BK;                                             \
        _Pragma("unroll")                                                     \
        for (int i = 0; i < 2; i++) {                                         \
            int p = tid + i * NTHREADS;                                       \
            int m = p >> 3, kq = (p & 7) * 4;                                 \
            va[i] = *(const float4*)((Abase) + (size_t)m * FF + k0 + kq);     \
        }                                                                     \
    }
#define STS_A(slot)                                                           \
    {                                                                         \
        _Pragma("unroll")                                                     \
        for (int i = 0; i < 2; i++) {                                         \
            int p = tid + i * NTHREADS;                                       \
            int m = p >> 3, kq = (p & 7) * 4;                                 \
            uint2 v = make_uint2(packh2(va[i].x, va[i].y),                    \
                                 packh2(va[i].z, va[i].w));                   \
            *(uint2*)(Ash + (slot) * (BM * RSAH) + m * RSAH + kq) = v;        \
        }                                                                     \
    }
#define ISSUE_B(kt, slot)                                                     \
    {                                                                         \
        const int k0 = (kt) * BK;                                             \
        _Pragma("unroll")                                                     \
        for (int i = 0; i < 2; i++) {                                         \
            int p = tid + i * NTHREADS;                                       \
            int n = p >> 2, k8 = (p & 3) * 8;                                 \
            CP16(bB + (slot) * B_ST_BYTES + (n * RSB + k8) * 2,               \
                 g_Bth + (size_t)n * FF + k0 + k8);                           \
        }                                                                     \
    }

    while (u < u1) {
        const int tile = u / KUNITS;
        const int kbeg = u - tile * KUNITS;
        const int seg  = min(KUNITS - kbeg, u1 - u);
        const int kend = kbeg + seg;
        const int row0 = tile * BM;
        const float* Abase = hmat + (size_t)row0 * FF;

        // B prologue: 3 stages in flight
#pragma unroll
        for (int s = 0; s < 3; s++) {
            if (s < seg) ISSUE_B(kbeg + s, s);
            CP_COMMIT();
        }
        // A prologue: tile kbeg into slot 0; kbeg+1 staged in regs
        LDG_A(Abase, kbeg);
        STS_A(0);
        if (kbeg + 1 < kend) LDG_A(Abase, kbeg + 1);

        float acc[2][8][4];
#pragma unroll
        for (int i = 0; i < 2; i++)
#pragma unroll
            for (int j = 0; j < 8; j++)
#pragma unroll
                for (int q = 0; q < 4; q++) acc[i][j][q] = 0.f;

        for (int kt = kbeg; kt < kend; kt++) {
            const int j    = kt - kbeg;
            const int slot = j & (NSTG - 1);
            CP_WAIT2();
            __syncthreads();
            if (kt + 3 < kend) ISSUE_B(kt + 3, (slot + 3) & (NSTG - 1));
            CP_COMMIT();
            if (kt + 1 < kend) STS_A((slot + 1) & (NSTG - 1));
            if (kt + 2 < kend) LDG_A(Abase, kt + 2);

            const uint32_t aS = aB + slot * A_ST_BYTES;
            const uint32_t bS = bB + slot * B_ST_BYTES;
            const int rlo = lane & 15;
            const int chi = (lane >> 4) * 8;
            const int j8  = lane & 7;
            const int mi  = lane >> 3;

            // A fragments for both ks upfront (4 ldmatrix.x4)
            unsigned af[2][2][4];
#pragma unroll
            for (int ks = 0; ks < 2; ks++)
#pragma unroll
                for (int mt = 0; mt < 2; mt++) {
                    const int mrow = wm * 32 + mt * 16;
                    uint32_t ad = aS +
                        ((mrow + rlo) * RSAH + ks * 16 + chi) * 2;
                    asm volatile(
                        "ldmatrix.sync.aligned.m8n8.x4.shared.b16 {%0,%1,%2,%3}, [%4];"
                        : "=r"(af[ks][mt][0]), "=r"(af[ks][mt][1]),
                          "=r"(af[ks][mt][2]), "=r"(af[ks][mt][3])
                        : "r"(ad));
                }

#pragma unroll
            for (int ks = 0; ks < 2; ks++) {
                const int kb = ks * 16;
                unsigned b[8][2];
#pragma unroll
                for (int pr = 0; pr < 4; pr++) {
                    const int n8 = wn * 64 + pr * 16;
                    uint32_t ad = bS +
                        ((n8 + (mi >> 1) * 8 + j8) * RSB + kb + (mi & 1) * 8) * 2;
                    asm volatile(
                        "ldmatrix.sync.aligned.m8n8.x4.shared.b16 {%0,%1,%2,%3}, [%4];"
                        : "=r"(b[2 * pr][0]), "=r"(b[2 * pr][1]),
                          "=r"(b[2 * pr + 1][0]), "=r"(b[2 * pr + 1][1])
                        : "r"(ad));
                }
#pragma unroll
                for (int mt = 0; mt < 2; mt++)
#pragma unroll
                    for (int nt = 0; nt < 8; nt++)
                        mma_f16(acc[mt][nt], af[ks][mt], b[nt]);
            }
        }
        __syncthreads();   // protect slots before next segment's prologue

        // flush tile segment via atomicAdd
#pragma unroll
        for (int mt = 0; mt < 2; mt++) {
            int r = row0 + wm * 32 + mt * 16 + (lane >> 2);
#pragma unroll
            for (int nt = 0; nt < 8; nt++) {
                int cc = wn * 64 + nt * 8 + (lane & 3) * 2;
                atomicAdd(&g_Wh[(size_t)r * NT + cc],           acc[mt][nt][0]);
                atomicAdd(&g_Wh[(size_t)r * NT + cc + 1],       acc[mt][nt][1]);
                atomicAdd(&g_Wh[(size_t)(r + 8) * NT + cc],     acc[mt][nt][2]);
                atomicAdd(&g_Wh[(size_t)(r + 8) * NT + cc + 1], acc[mt][nt][3]);
            }
        }

        u += seg;
    }
#undef LDG_A
#undef STS_A
#undef ISSUE_B
}

// ---------------------------------------------------------------------------
// Kernel B: GAT attention + ELU. grid (256,4), 256 threads, 5 blocks/SM.
// ---------------------------------------------------------------------------
#define NP 52
__global__ __launch_bounds__(256, 5)
void attn_kernel(const float* __restrict__ a, float* __restrict__ out)
{
    __shared__ float sWh[NP][68];
    __shared__ float sA2[NP][68];
    __shared__ float sE[NP][NP];
    __shared__ float sS1[NN];
    __shared__ unsigned char sAdj[NN * NN];

    const int b    = blockIdx.x;
    const int h    = blockIdx.y;
    const int tid  = threadIdx.x;
    const int lane = tid & 31;
    const int wid  = tid >> 5;

    {
        const unsigned* src = (const unsigned*)(g_adj + (size_t)b * NN * NN);
        unsigned* dst = (unsigned*)sAdj;
        for (int i = tid; i < NN * NN / 4; i += 256) dst[i] = src[i];
    }

    if (tid < 2 * 68) {
        int r = 50 + tid / 68, cidx = tid % 68;
        sWh[r][cidx] = 0.f;
        sA2[r][cidx] = 0.f;
    }

    for (int idx = tid; idx < NN * OO / 4; idx += 256) {
        int n_ = idx >> 4;
        int o4 = (idx & 15) * 4;
        float4 w  = *(const float4*)&g_Wh[(size_t)(b * NN + n_) * NT + h * OO + o4];
        float4 av = *(const float4*)&a[(size_t)(h * NN + n_) * (2 * OO) + OO + o4];
        *(float4*)&sWh[n_][o4] = w;
        *(float4*)&sA2[n_][o4] = av;
    }
    __syncthreads();

    for (int n_ = wid; n_ < NN; n_ += 8) {
        float a1v0 = a[(size_t)(h * NN + n_) * (2 * OO) + lane];
        float a1v1 = a[(size_t)(h * NN + n_) * (2 * OO) + lane + 32];
        float v = sWh[n_][lane] * a1v0 + sWh[n_][lane + 32] * a1v1;
#pragma unroll
        for (int off = 16; off; off >>= 1) v += __shfl_xor_sync(0xffffffffu, v, off);
        if (lane == 0) sS1[n_] = v;
    }

    if (tid < 169) {
        const int n0 = (tid / 13) * 4;
        const int m0 = (tid % 13) * 4;
        float acc[4][4];
#pragma unroll
        for (int i = 0; i < 4; i++)
#pragma unroll
            for (int j = 0; j < 4; j++) acc[i][j] = 0.f;
#pragma unroll 8
        for (int o = 0; o < OO; o++) {
            float av[4], wv[4];
#pragma unroll
            for (int i = 0; i < 4; i++) av[i] = sA2[n0 + i][o];
#pragma unroll
            for (int j = 0; j < 4; j++) wv[j] = sWh[m0 + j][o];
#pragma unroll
            for (int i = 0; i < 4; i++)
#pragma unroll
                for (int j = 0; j < 4; j++)
                    acc[i][j] = fmaf(av[i], wv[j], acc[i][j]);
        }
#pragma unroll
        for (int i = 0; i < 4; i++)
#pragma unroll
            for (int j = 0; j < 4; j++) sE[n0 + i][m0 + j] = acc[i][j];
    }
    __syncthreads();

    for (int n_ = wid; n_ < NN; n_ += 8) {
        float s1v = sS1[n_];
        int m0 = lane, m1 = lane + 32;
        float t0 = s1v + sE[n_][m0];
        t0 = (t0 >= 0.f) ? t0 : 0.2f * t0;
        float v0 = sAdj[n_ * NN + m0] ? t0 : -9e15f;
        float v1 = -9e15f;
        if (m1 < NN) {
            float t1 = s1v + sE[n_][m1];
            t1 = (t1 >= 0.f) ? t1 : 0.2f * t1;
            v1 = sAdj[n_ * NN + m1] ? t1 : -9e15f;
        }
        float mx = fmaxf(v0, v1);
#pragma unroll
        for (int off = 16; off; off >>= 1)
            mx = fmaxf(mx, __shfl_xor_sync(0xffffffffu, mx, off));
        float e0_ = __expf(v0 - mx);
        float e1_ = (m1 < NN) ? __expf(v1 - mx) : 0.f;
        float sum = e0_ + e1_;
#pragma unroll
        for (int off = 16; off; off >>= 1)
            sum += __shfl_xor_sync(0xffffffffu, sum, off);
        float inv = 1.f / sum;
        sE[n_][m0] = e0_ * inv;
        if (m1 < NN) sE[n_][m1] = e1_ * inv;
    }
    __syncthreads();

    if (tid < 208) {
        const int n0 = (tid / 16) * 4;
        const int o4 = (tid % 16) * 4;
        float4 acc[4];
#pragma unroll
        for (int i = 0; i < 4; i++) acc[i] = make_float4(0.f, 0.f, 0.f, 0.f);
#pragma unroll 5
        for (int m = 0; m < NN; m++) {
            float4 wv = *(const float4*)&sWh[m][o4];
#pragma unroll
            for (int i = 0; i < 4; i++) {
                float at = sE[n0 + i][m];
                acc[i].x = fmaf(at, wv.x, acc[i].x);
                acc[i].y = fmaf(at, wv.y, acc[i].y);
                acc[i].z = fmaf(at, wv.z, acc[i].z);
                acc[i].w = fmaf(at, wv.w, acc[i].w);
            }
        }
#pragma unroll
        for (int i = 0; i < 4; i++) {
            int n_ = n0 + i;
            if (n_ < NN) {
                float4 wv = *(const float4*)&sWh[n_][o4];
                float4 v = make_float4(acc[i].x + 0.3f * wv.x,
                                       acc[i].y + 0.3f * wv.y,
                                       acc[i].z + 0.3f * wv.z,
                                       acc[i].w + 0.3f * wv.w);
                v.x = (v.x > 0.f) ? v.x : expm1f(v.x);
                v.y = (v.y > 0.f) ? v.y : expm1f(v.y);
                v.z = (v.z > 0.f) ? v.z : expm1f(v.z);
                v.w = (v.w > 0.f) ? v.w : expm1f(v.w);
                *(float4*)&out[(size_t)(b * NN + n_) * NT + h * OO + o4] = v;
            }
        }
    }
}

// ---------------------------------------------------------------------------
extern "C" void kernel_launch(void* const* d_in, const int* in_sizes, int n_in,
                              void* d_out, int out_size)
{
    const float* h_    = (const float*)d_in[0];  // (B, N, F)
    const float* probs = (const float*)d_in[1];  // (B, N*N)
    const float* u_    = (const float*)d_in[2];  // (B, N*N, 2)
    const float* W_    = (const float*)d_in[3];  // (H, F, O)
    const float* a_    = (const float*)d_in[4];  // (H, N, 2*O)
    float* out = (float*)d_out;

    zero_kernel<<<592, 256>>>();
    adj_kernel<<<(BB * NN * NN + 255) / 256, 256>>>(probs, u_);

    dim3 tgrid(FF / 32, HH);
    wT_kernel<<<tgrid, 256>>>(W_);

    cudaFuncSetAttribute(gemm_f16, cudaFuncAttributeMaxDynamicSharedMemorySize,
                         SMEM_BYTES);
    gemm_f16<<<GRID_G, NTHREADS, SMEM_BYTES>>>(h_);

    dim3 agrid(BB, HH);
    attn_kernel<<<agrid, 256>>>(a_, out);
}

// round 11
// speedup vs baseline: 1.1189x; 1.0212x over previous
#include <cuda_runtime.h>
#include <cuda_fp16.h>
#include <math.h>
#include <stdint.h>

// Problem constants
#define BB 256
#define NN 50
#define FF 6144
#define HH 4
#define OO 64
#define NT (HH*OO)          // 256
#define MT (BB*NN)          // 12800

// GEMM tiling: CTA tile 128 x 256 (full width), fp16 smem both operands
#define BM 128
#define BN 256
#define BK 32
#define RSAH 40                         // A row stride (halves)
#define RSB 40                          // B row stride (halves)
#define NSTG 4
#define A_ST_BYTES (BM * RSAH * 2)      // 10240
#define B_ST_BYTES (BN * RSB  * 2)      // 20480
#define SMEM_BYTES (NSTG * (A_ST_BYTES + B_ST_BYTES))   // 122880
#define NTILES (MT/BM)                  // 100
#define KUNITS (FF/BK)                  // 192
#define UNITS_TOTAL (NTILES * KUNITS)   // 19200
#define GRID_G 148
#define NTHREADS 512

__device__ float  g_Wh[(size_t)MT * NT];              // 13.1 MB, zeroed per launch
__device__ __half g_Bth[(size_t)NT * FF];             // 3.1 MB fp16 B, K-major
__device__ unsigned char g_adj[(size_t)BB * NN * NN]; // 640 KB

__device__ __forceinline__ uint32_t smem_u32(const void* p) {
    uint32_t a;
    asm("{ .reg .u64 t; cvta.to.shared.u64 t, %1; cvt.u32.u64 %0, t; }" : "=r"(a) : "l"(p));
    return a;
}
__device__ __forceinline__ unsigned packh2(float x, float y) {
    half2 h = __floats2half2_rn(x, y);
    return *(unsigned*)&h;
}
__device__ __forceinline__ void mma_f16(float c[4],
                                        const unsigned a[4],
                                        unsigned b0, unsigned b1) {
    asm volatile(
        "mma.sync.aligned.m16n8k16.row.col.f32.f16.f16.f32 "
        "{%0,%1,%2,%3}, {%4,%5,%6,%7}, {%8,%9}, {%0,%1,%2,%3};"
        : "+f"(c[0]), "+f"(c[1]), "+f"(c[2]), "+f"(c[3])
        : "r"(a[0]), "r"(a[1]), "r"(a[2]), "r"(a[3]),
          "r"(b0), "r"(b1));
}
#define CP16(dst, src) \
    asm volatile("cp.async.cg.shared.global [%0], [%1], 16;" :: "r"(dst), "l"(src))
#define CP_COMMIT() asm volatile("cp.async.commit_group;" ::: "memory")
#define CP_WAIT2()  asm volatile("cp.async.wait_group 2;"  ::: "memory")
#define LDSM_X4(r0, r1, r2, r3, ad)                                           \
    asm volatile("ldmatrix.sync.aligned.m8n8.x4.shared.b16 {%0,%1,%2,%3}, [%4];" \
        : "=r"(r0), "=r"(r1), "=r"(r2), "=r"(r3) : "r"(ad))

// ---------------------------------------------------------------------------
__global__ void zero_kernel()
{
    size_t i = (size_t)blockIdx.x * blockDim.x + threadIdx.x;
    float4* p = (float4*)g_Wh;
    size_t n4 = (size_t)MT * NT / 4;
    for (; i < n4; i += (size_t)gridDim.x * blockDim.x)
        p[i] = make_float4(0.f, 0.f, 0.f, 0.f);
}

// ---------------------------------------------------------------------------
__global__ __launch_bounds__(256)
void adj_kernel(const float* __restrict__ probs, const float* __restrict__ u)
{
    int idx = blockIdx.x * 256 + threadIdx.x;
    if (idx >= BB * NN * NN) return;
    float p = probs[idx];
    float2 uv = *(const float2*)&u[(size_t)idx * 2];
    float x0 = p, x1 = 1.f - p;
    float mx = fmaxf(x0, x1);
    float e0 = __expf(x0 - mx), e1 = __expf(x1 - mx);
    float inv = 1.f / (e0 + e1);
    float l0 = __logf(e0 * inv + 1e-5f);
    float l1 = __logf(e1 * inv + 1e-5f);
    float g0 = -__logf(-__logf(uv.x + 1e-10f) + 1e-10f);
    float g1 = -__logf(-__logf(uv.y + 1e-10f) + 1e-10f);
    g_adj[idx] = (l0 + g0 >= l1 + g1) ? 1 : 0;
}

// ---------------------------------------------------------------------------
// W (H,F,O) fp32 -> g_Bth[n=h*64+o][k=f] fp16 (transpose + convert)
// ---------------------------------------------------------------------------
__global__ __launch_bounds__(256)
void wT_kernel(const float* __restrict__ W)
{
    __shared__ float t[32][65];
    const int f0 = blockIdx.x * 32;
    const int h  = blockIdx.y;
    for (int i = threadIdx.x; i < 32 * 64; i += 256) {
        int fi = i >> 6, o = i & 63;
        t[fi][o] = W[((size_t)h * FF + f0 + fi) * OO + o];
    }
    __syncthreads();
    for (int i = threadIdx.x; i < 32 * 64; i += 256) {
        int o = i >> 5, fi = i & 31;
        g_Bth[(size_t)(h * 64 + o) * FF + f0 + fi] = __float2half_rn(t[fi][o]);
    }
}

// ---------------------------------------------------------------------------
// Kernel A: persistent fp16 GEMM. Fragments software-pipelined (LDSM of the
// next pr-pair issues before the MMAs of the current pair).
// ---------------------------------------------------------------------------
__global__ __launch_bounds__(NTHREADS, 1)
void gemm_f16(const float* __restrict__ hmat)
{
    extern __shared__ char smraw[];
    __half* Ash = (__half*)smraw;                          // [NSTG][BM][RSAH]
    __half* Bsh = (__half*)(smraw + NSTG * A_ST_BYTES);    // [NSTG][BN][RSB]
    const uint32_t aB = smem_u32(Ash);
    const uint32_t bB = smem_u32(Bsh);

    const int tid  = threadIdx.x;
    const int lane = tid & 31;
    const int wid  = tid >> 5;
    const int wm   = wid & 3;              // 4 x 32 m
    const int wn   = wid >> 2;             // 4 x 64 n

    const int c  = blockIdx.x;
    int u        = (int)(((long long)UNITS_TOTAL * c) / GRID_G);
    const int u1 = (int)(((long long)UNITS_TOTAL * (c + 1)) / GRID_G);

    float4 va[2];

#define LDG_A(Abase, kt)                                                      \
    {                                                                         \
        const int k0 = (kt) * BK;                                             \
        _Pragma("unroll")                                                     \
        for (int i = 0; i < 2; i++) {                                         \
            int p = tid + i * NTHREADS;                                       \
            int m = p >> 3, kq = (p & 7) * 4;                                 \
            va[i] = *(const float4*)((Abase) + (size_t)m * FF + k0 + kq);     \
        }                                                                     \
    }
#define STS_A(slot)                                                           \
    {                                                                         \
        _Pragma("unroll")                                                     \
        for (int i = 0; i < 2; i++) {                                         \
            int p = tid + i * NTHREADS;                                       \
            int m = p >> 3, kq = (p & 7) * 4;                                 \
            uint2 v = make_uint2(packh2(va[i].x, va[i].y),                    \
                                 packh2(va[i].z, va[i].w));                   \
            *(uint2*)(Ash + (slot) * (BM * RSAH) + m * RSAH + kq) = v;        \
        }                                                                     \
    }
#define ISSUE_B(kt, slot)                                                     \
    {                                                                         \
        const int k0 = (kt) * BK;                                             \
        _Pragma("unroll")                                                     \
        for (int i = 0; i < 2; i++) {                                         \
            int p = tid + i * NTHREADS;                                       \
            int n = p >> 2, k8 = (p & 3) * 8;                                 \
            CP16(bB + (slot) * B_ST_BYTES + (n * RSB + k8) * 2,               \
                 g_Bth + (size_t)n * FF + k0 + k8);                           \
        }                                                                     \
    }

    while (u < u1) {
        const int tile = u / KUNITS;
        const int kbeg = u - tile * KUNITS;
        const int seg  = min(KUNITS - kbeg, u1 - u);
        const int kend = kbeg + seg;
        const int row0 = tile * BM;
        const float* Abase = hmat + (size_t)row0 * FF;

        // B prologue: 3 stages in flight
#pragma unroll
        for (int s = 0; s < 3; s++) {
            if (s < seg) ISSUE_B(kbeg + s, s);
            CP_COMMIT();
        }
        // A prologue
        LDG_A(Abase, kbeg);
        STS_A(0);
        if (kbeg + 1 < kend) LDG_A(Abase, kbeg + 1);

        float acc[2][8][4];
#pragma unroll
        for (int i = 0; i < 2; i++)
#pragma unroll
            for (int j = 0; j < 8; j++)
#pragma unroll
                for (int q = 0; q < 4; q++) acc[i][j][q] = 0.f;

        for (int kt = kbeg; kt < kend; kt++) {
            const int j    = kt - kbeg;
            const int slot = j & (NSTG - 1);
            CP_WAIT2();
            __syncthreads();
            if (kt + 3 < kend) ISSUE_B(kt + 3, (slot + 3) & (NSTG - 1));
            CP_COMMIT();
            if (kt + 1 < kend) STS_A((slot + 1) & (NSTG - 1));
            if (kt + 2 < kend) LDG_A(Abase, kt + 2);

            const uint32_t aS = aB + slot * A_ST_BYTES;
            const uint32_t bS = bB + slot * B_ST_BYTES;
            const int rlo = lane & 15;
            const int chi = (lane >> 4) * 8;
            const int j8  = lane & 7;
            const int mi  = lane >> 3;
            const uint32_t bRow = bS +
                ((wn * 64 + (mi >> 1) * 8 + j8) * RSB + (mi & 1) * 8) * 2;

            // A fragments for both ks upfront (4 ldmatrix.x4)
            unsigned af[2][2][4];
#pragma unroll
            for (int ks = 0; ks < 2; ks++)
#pragma unroll
                for (int mt = 0; mt < 2; mt++) {
                    const int mrow = wm * 32 + mt * 16;
                    uint32_t ad = aS + ((mrow + rlo) * RSAH + ks * 16 + chi) * 2;
                    LDSM_X4(af[ks][mt][0], af[ks][mt][1],
                            af[ks][mt][2], af[ks][mt][3], ad);
                }

            // B fragments: double-buffered per pr pair; LDSM(pr+1) before MMA(pr)
            unsigned bfr[2][4];
#pragma unroll
            for (int ks = 0; ks < 2; ks++) {
                const int kboff = ks * 16 * 2;     // byte offset for this ks
                LDSM_X4(bfr[0][0], bfr[0][1], bfr[0][2], bfr[0][3],
                        bRow + kboff);
#pragma unroll
                for (int pr = 0; pr < 4; pr++) {
                    const int cb = pr & 1;
                    if (pr < 3) {
                        LDSM_X4(bfr[cb ^ 1][0], bfr[cb ^ 1][1],
                                bfr[cb ^ 1][2], bfr[cb ^ 1][3],
                                bRow + kboff + (pr + 1) * 16 * RSB * 2);
                    }
#pragma unroll
                    for (int mt = 0; mt < 2; mt++) {
                        mma_f16(acc[mt][2 * pr],     af[ks][mt], bfr[cb][0], bfr[cb][1]);
                        mma_f16(acc[mt][2 * pr + 1], af[ks][mt], bfr[cb][2], bfr[cb][3]);
                    }
                }
            }
        }
        __syncthreads();   // protect slots before next segment's prologue

        // flush tile segment via atomicAdd
#pragma unroll
        for (int mt = 0; mt < 2; mt++) {
            int r = row0 + wm * 32 + mt * 16 + (lane >> 2);
#pragma unroll
            for (int nt = 0; nt < 8; nt++) {
                int cc = wn * 64 + nt * 8 + (lane & 3) * 2;
                atomicAdd(&g_Wh[(size_t)r * NT + cc],           acc[mt][nt][0]);
                atomicAdd(&g_Wh[(size_t)r * NT + cc + 1],       acc[mt][nt][1]);
                atomicAdd(&g_Wh[(size_t)(r + 8) * NT + cc],     acc[mt][nt][2]);
                atomicAdd(&g_Wh[(size_t)(r + 8) * NT + cc + 1], acc[mt][nt][3]);
            }
        }

        u += seg;
    }
#undef LDG_A
#undef STS_A
#undef ISSUE_B
}

// ---------------------------------------------------------------------------
// Kernel B: GAT attention + ELU. grid (256,4), 256 threads, 5 blocks/SM.
// ---------------------------------------------------------------------------
#define NP 52
__global__ __launch_bounds__(256, 5)
void attn_kernel(const float* __restrict__ a, float* __restrict__ out)
{
    __shared__ float sWh[NP][68];
    __shared__ float sA2[NP][68];
    __shared__ float sE[NP][NP];
    __shared__ float sS1[NN];
    __shared__ unsigned char sAdj[NN * NN];

    const int b    = blockIdx.x;
    const int h    = blockIdx.y;
    const int tid  = threadIdx.x;
    const int lane = tid & 31;
    const int wid  = tid >> 5;

    {
        const unsigned* src = (const unsigned*)(g_adj + (size_t)b * NN * NN);
        unsigned* dst = (unsigned*)sAdj;
        for (int i = tid; i < NN * NN / 4; i += 256) dst[i] = src[i];
    }

    if (tid < 2 * 68) {
        int r = 50 + tid / 68, cidx = tid % 68;
        sWh[r][cidx] = 0.f;
        sA2[r][cidx] = 0.f;
    }

    for (int idx = tid; idx < NN * OO / 4; idx += 256) {
        int n_ = idx >> 4;
        int o4 = (idx & 15) * 4;
        float4 w  = *(const float4*)&g_Wh[(size_t)(b * NN + n_) * NT + h * OO + o4];
        float4 av = *(const float4*)&a[(size_t)(h * NN + n_) * (2 * OO) + OO + o4];
        *(float4*)&sWh[n_][o4] = w;
        *(float4*)&sA2[n_][o4] = av;
    }
    __syncthreads();

    for (int n_ = wid; n_ < NN; n_ += 8) {
        float a1v0 = a[(size_t)(h * NN + n_) * (2 * OO) + lane];
        float a1v1 = a[(size_t)(h * NN + n_) * (2 * OO) + lane + 32];
        float v = sWh[n_][lane] * a1v0 + sWh[n_][lane + 32] * a1v1;
#pragma unroll
        for (int off = 16; off; off >>= 1) v += __shfl_xor_sync(0xffffffffu, v, off);
        if (lane == 0) sS1[n_] = v;
    }

    if (tid < 169) {
        const int n0 = (tid / 13) * 4;
        const int m0 = (tid % 13) * 4;
        float acc[4][4];
#pragma unroll
        for (int i = 0; i < 4; i++)
#pragma unroll
            for (int j = 0; j < 4; j++) acc[i][j] = 0.f;
#pragma unroll 8
        for (int o = 0; o < OO; o++) {
            float av[4], wv[4];
#pragma unroll
            for (int i = 0; i < 4; i++) av[i] = sA2[n0 + i][o];
#pragma unroll
            for (int j = 0; j < 4; j++) wv[j] = sWh[m0 + j][o];
#pragma unroll
            for (int i = 0; i < 4; i++)
#pragma unroll
                for (int j = 0; j < 4; j++)
                    acc[i][j] = fmaf(av[i], wv[j], acc[i][j]);
        }
#pragma unroll
        for (int i = 0; i < 4; i++)
#pragma unroll
            for (int j = 0; j < 4; j++) sE[n0 + i][m0 + j] = acc[i][j];
    }
    __syncthreads();

    for (int n_ = wid; n_ < NN; n_ += 8) {
        float s1v = sS1[n_];
        int m0 = lane, m1 = lane + 32;
        float t0 = s1v + sE[n_][m0];
        t0 = (t0 >= 0.f) ? t0 : 0.2f * t0;
        float v0 = sAdj[n_ * NN + m0] ? t0 : -9e15f;
        float v1 = -9e15f;
        if (m1 < NN) {
            float t1 = s1v + sE[n_][m1];
            t1 = (t1 >= 0.f) ? t1 : 0.2f * t1;
            v1 = sAdj[n_ * NN + m1] ? t1 : -9e15f;
        }
        float mx = fmaxf(v0, v1);
#pragma unroll
        for (int off = 16; off; off >>= 1)
            mx = fmaxf(mx, __shfl_xor_sync(0xffffffffu, mx, off));
        float e0_ = __expf(v0 - mx);
        float e1_ = (m1 < NN) ? __expf(v1 - mx) : 0.f;
        float sum = e0_ + e1_;
#pragma unroll
        for (int off = 16; off; off >>= 1)
            sum += __shfl_xor_sync(0xffffffffu, sum, off);
        float inv = 1.f / sum;
        sE[n_][m0] = e0_ * inv;
        if (m1 < NN) sE[n_][m1] = e1_ * inv;
    }
    __syncthreads();

    if (tid < 208) {
        const int n0 = (tid / 16) * 4;
        const int o4 = (tid % 16) * 4;
        float4 acc[4];
#pragma unroll
        for (int i = 0; i < 4; i++) acc[i] = make_float4(0.f, 0.f, 0.f, 0.f);
#pragma unroll 5
        for (int m = 0; m < NN; m++) {
            float4 wv = *(const float4*)&sWh[m][o4];
#pragma unroll
            for (int i = 0; i < 4; i++) {
                float at = sE[n0 + i][m];
                acc[i].x = fmaf(at, wv.x, acc[i].x);
                acc[i].y = fmaf(at, wv.y, acc[i].y);
                acc[i].z = fmaf(at, wv.z, acc[i].z);
                acc[i].w = fmaf(at, wv.w, acc[i].w);
            }
        }
#pragma unroll
        for (int i = 0; i < 4; i++) {
            int n_ = n0 + i;
            if (n_ < NN) {
                float4 wv = *(const float4*)&sWh[n_][o4];
                float4 v = make_float4(acc[i].x + 0.3f * wv.x,
                                       acc[i].y + 0.3f * wv.y,
                                       acc[i].z + 0.3f * wv.z,
                                       acc[i].w + 0.3f * wv.w);
                v.x = (v.x > 0.f) ? v.x : expm1f(v.x);
                v.y = (v.y > 0.f) ? v.y : expm1f(v.y);
                v.z = (v.z > 0.f) ? v.z : expm1f(v.z);
                v.w = (v.w > 0.f) ? v.w : expm1f(v.w);
                *(float4*)&out[(size_t)(b * NN + n_) * NT + h * OO + o4] = v;
            }
        }
    }
}

// ---------------------------------------------------------------------------
extern "C" void kernel_launch(void* const* d_in, const int* in_sizes, int n_in,
                              void* d_out, int out_size)
{
    const float* h_    = (const float*)d_in[0];  // (B, N, F)
    const float* probs = (const float*)d_in[1];  // (B, N*N)
    const float* u_    = (const float*)d_in[2];  // (B, N*N, 2)
    const float* W_    = (const float*)d_in[3];  // (H, F, O)
    const float* a_    = (const float*)d_in[4];  // (H, N, 2*O)
    float* out = (float*)d_out;

    zero_kernel<<<592, 256>>>();
    adj_kernel<<<(BB * NN * NN + 255) / 256, 256>>>(probs, u_);

    dim3 tgrid(FF / 32, HH);
    wT_kernel<<<tgrid, 256>>>(W_);

    cudaFuncSetAttribute(gemm_f16, cudaFuncAttributeMaxDynamicSharedMemorySize,
                         SMEM_BYTES);
    gemm_f16<<<GRID_G, NTHREADS, SMEM_BYTES>>>(h_);

    dim3 agrid(BB, HH);
    attn_kernel<<<agrid, 256>>>(a_, out);
}

// round 12
// speedup vs baseline: 1.2248x; 1.0947x over previous
#include <cuda_runtime.h>
#include <cuda_fp16.h>
#include <math.h>
#include <stdint.h>

// Problem constants
#define BB 256
#define NN 50
#define FF 6144
#define HH 4
#define OO 64
#define NT (HH*OO)          // 256
#define MT (BB*NN)          // 12800

// GEMM tiling: CTA tile 128 x 256 (full width), BK=64 per phase
#define BM 128
#define BN 256
#define BK 64
#define RSAH 72                         // A row stride (halves)
#define RSB 72                          // B row stride (halves)
#define NSTG 3
#define A_ST_BYTES (BM * RSAH * 2)      // 18432
#define B_ST_BYTES (BN * RSB  * 2)      // 36864
#define SMEM_BYTES (NSTG * (A_ST_BYTES + B_ST_BYTES))   // 165888
#define NTILES (MT/BM)                  // 100
#define KUNITS (FF/BK)                  // 96
#define UNITS_TOTAL (NTILES * KUNITS)   // 9600
#define GRID_G 148
#define NTHREADS 512

__device__ float  g_Wh[(size_t)MT * NT];              // 13.1 MB, zeroed per launch
__device__ __half g_Bth[(size_t)NT * FF];             // 3.1 MB fp16 B, K-major
__device__ unsigned char g_adj[(size_t)BB * NN * NN]; // 640 KB

__device__ __forceinline__ uint32_t smem_u32(const void* p) {
    uint32_t a;
    asm("{ .reg .u64 t; cvta.to.shared.u64 t, %1; cvt.u32.u64 %0, t; }" : "=r"(a) : "l"(p));
    return a;
}
__device__ __forceinline__ unsigned packh2(float x, float y) {
    half2 h = __floats2half2_rn(x, y);
    return *(unsigned*)&h;
}
__device__ __forceinline__ void mma_f16(float c[4],
                                        const unsigned a[4],
                                        unsigned b0, unsigned b1) {
    asm volatile(
        "mma.sync.aligned.m16n8k16.row.col.f32.f16.f16.f32 "
        "{%0,%1,%2,%3}, {%4,%5,%6,%7}, {%8,%9}, {%0,%1,%2,%3};"
        : "+f"(c[0]), "+f"(c[1]), "+f"(c[2]), "+f"(c[3])
        : "r"(a[0]), "r"(a[1]), "r"(a[2]), "r"(a[3]),
          "r"(b0), "r"(b1));
}
#define CP16(dst, src) \
    asm volatile("cp.async.cg.shared.global [%0], [%1], 16;" :: "r"(dst), "l"(src))
#define CP_COMMIT() asm volatile("cp.async.commit_group;" ::: "memory")
#define CP_WAIT1()  asm volatile("cp.async.wait_group 1;"  ::: "memory")
#define LDSM_X4(r0, r1, r2, r3, ad)                                           \
    asm volatile("ldmatrix.sync.aligned.m8n8.x4.shared.b16 {%0,%1,%2,%3}, [%4];" \
        : "=r"(r0), "=r"(r1), "=r"(r2), "=r"(r3) : "r"(ad))

// ---------------------------------------------------------------------------
__global__ void zero_kernel()
{
    size_t i = (size_t)blockIdx.x * blockDim.x + threadIdx.x;
    float4* p = (float4*)g_Wh;
    size_t n4 = (size_t)MT * NT / 4;
    for (; i < n4; i += (size_t)gridDim.x * blockDim.x)
        p[i] = make_float4(0.f, 0.f, 0.f, 0.f);
}

// ---------------------------------------------------------------------------
__global__ __launch_bounds__(256)
void adj_kernel(const float* __restrict__ probs, const float* __restrict__ u)
{
    int idx = blockIdx.x * 256 + threadIdx.x;
    if (idx >= BB * NN * NN) return;
    float p = probs[idx];
    float2 uv = *(const float2*)&u[(size_t)idx * 2];
    float x0 = p, x1 = 1.f - p;
    float mx = fmaxf(x0, x1);
    float e0 = __expf(x0 - mx), e1 = __expf(x1 - mx);
    float inv = 1.f / (e0 + e1);
    float l0 = __logf(e0 * inv + 1e-5f);
    float l1 = __logf(e1 * inv + 1e-5f);
    float g0 = -__logf(-__logf(uv.x + 1e-10f) + 1e-10f);
    float g1 = -__logf(-__logf(uv.y + 1e-10f) + 1e-10f);
    g_adj[idx] = (l0 + g0 >= l1 + g1) ? 1 : 0;
}

// ---------------------------------------------------------------------------
// W (H,F,O) fp32 -> g_Bth[n=h*64+o][k=f] fp16 (transpose + convert)
// ---------------------------------------------------------------------------
__global__ __launch_bounds__(256)
void wT_kernel(const float* __restrict__ W)
{
    __shared__ float t[32][65];
    const int f0 = blockIdx.x * 32;
    const int h  = blockIdx.y;
    for (int i = threadIdx.x; i < 32 * 64; i += 256) {
        int fi = i >> 6, o = i & 63;
        t[fi][o] = W[((size_t)h * FF + f0 + fi) * OO + o];
    }
    __syncthreads();
    for (int i = threadIdx.x; i < 32 * 64; i += 256) {
        int o = i >> 5, fi = i & 31;
        g_Bth[(size_t)(h * 64 + o) * FF + f0 + fi] = __float2half_rn(t[fi][o]);
    }
}

// ---------------------------------------------------------------------------
// Kernel A: persistent fp16 GEMM, BK=64 phases (one barrier per 64 K).
// ---------------------------------------------------------------------------
__global__ __launch_bounds__(NTHREADS, 1)
void gemm_f16(const float* __restrict__ hmat)
{
    extern __shared__ char smraw[];
    __half* Ash = (__half*)smraw;                          // [NSTG][BM][RSAH]
    __half* Bsh = (__half*)(smraw + NSTG * A_ST_BYTES);    // [NSTG][BN][RSB]
    const uint32_t aB = smem_u32(Ash);
    const uint32_t bB = smem_u32(Bsh);

    const int tid  = threadIdx.x;
    const int lane = tid & 31;
    const int wid  = tid >> 5;
    const int wm   = wid & 3;              // 4 x 32 m
    const int wn   = wid >> 2;             // 4 x 64 n

    const int c  = blockIdx.x;
    int u        = (int)(((long long)UNITS_TOTAL * c) / GRID_G);
    const int u1 = (int)(((long long)UNITS_TOTAL * (c + 1)) / GRID_G);

    float4 va[4];

    // A phase: 128m x 64k floats = 2048 float4; p -> m = p>>4, kq = (p&15)*4
    // B phase: 256n x 64k halves = 2048 int4;   p -> n = p>>3, k8 = (p&7)*8
#define LDG_A(Abase, kt)                                                      \
    {                                                                         \
        const int k0 = (kt) * BK;                                             \
        _Pragma("unroll")                                                     \
        for (int i = 0; i < 4; i++) {                                         \
            int p = tid + i * NTHREADS;                                       \
            int m = p >> 4, kq = (p & 15) * 4;                                \
            va[i] = *(const float4*)((Abase) + (size_t)m * FF + k0 + kq);     \
        }                                                                     \
    }
#define STS_A(slot)                                                           \
    {                                                                         \
        _Pragma("unroll")                                                     \
        for (int i = 0; i < 4; i++) {                                         \
            int p = tid + i * NTHREADS;                                       \
            int m = p >> 4, kq = (p & 15) * 4;                                \
            uint2 v = make_uint2(packh2(va[i].x, va[i].y),                    \
                                 packh2(va[i].z, va[i].w));                   \
            *(uint2*)(Ash + (slot) * (BM * RSAH) + m * RSAH + kq) = v;        \
        }                                                                     \
    }
#define ISSUE_B(kt, slot)                                                     \
    {                                                                         \
        const int k0 = (kt) * BK;                                             \
        _Pragma("unroll")                                                     \
        for (int i = 0; i < 4; i++) {                                         \
            int p = tid + i * NTHREADS;                                       \
            int n = p >> 3, k8 = (p & 7) * 8;                                 \
            CP16(bB + (slot) * B_ST_BYTES + (n * RSB + k8) * 2,               \
                 g_Bth + (size_t)n * FF + k0 + k8);                           \
        }                                                                     \
    }

    while (u < u1) {
        const int tile = u / KUNITS;
        const int kbeg = u - tile * KUNITS;
        const int seg  = min(KUNITS - kbeg, u1 - u);
        const int kend = kbeg + seg;
        const int row0 = tile * BM;
        const float* Abase = hmat + (size_t)row0 * FF;

        // prologue: 2 B groups in flight; A phase 0 in smem, phase 1 in regs
#pragma unroll
        for (int s = 0; s < 2; s++) {
            if (s < seg) ISSUE_B(kbeg + s, s);
            CP_COMMIT();
        }
        LDG_A(Abase, kbeg);
        STS_A(0);
        if (kbeg + 1 < kend) LDG_A(Abase, kbeg + 1);

        float acc[2][8][4];
#pragma unroll
        for (int i = 0; i < 2; i++)
#pragma unroll
            for (int j = 0; j < 8; j++)
#pragma unroll
                for (int q = 0; q < 4; q++) acc[i][j][q] = 0.f;

        int slot = 0;
        for (int kt = kbeg; kt < kend; kt++) {
            CP_WAIT1();
            __syncthreads();
            {
                int s2 = slot + 2; if (s2 >= NSTG) s2 -= NSTG;
                if (kt + 2 < kend) ISSUE_B(kt + 2, s2);
                CP_COMMIT();
            }
            if (kt + 1 < kend) {
                int s1 = slot + 1; if (s1 >= NSTG) s1 -= NSTG;
                STS_A(s1);
            }
            if (kt + 2 < kend) LDG_A(Abase, kt + 2);

            const uint32_t aS = aB + slot * A_ST_BYTES;
            const uint32_t bS = bB + slot * B_ST_BYTES;
            const int rlo = lane & 15;
            const int chi = (lane >> 4) * 8;
            const int j8  = lane & 7;
            const int mi  = lane >> 3;
            const uint32_t bRow = bS +
                ((wn * 64 + (mi >> 1) * 8 + j8) * RSB + (mi & 1) * 8) * 2;

            // 4 ks sub-steps of K=16 each
#pragma unroll
            for (int ks = 0; ks < 4; ks++) {
                const int kboff = ks * 16 * 2;    // byte offset along K

                // A fragments for this ks (2 LDSM.x4)
                unsigned af[2][4];
#pragma unroll
                for (int mt = 0; mt < 2; mt++) {
                    const int mrow = wm * 32 + mt * 16;
                    uint32_t ad = aS + ((mrow + rlo) * RSAH + ks * 16 + chi) * 2;
                    LDSM_X4(af[mt][0], af[mt][1], af[mt][2], af[mt][3], ad);
                }

                // B fragments double-buffered per pr pair
                unsigned bfr[2][4];
                LDSM_X4(bfr[0][0], bfr[0][1], bfr[0][2], bfr[0][3],
                        bRow + kboff);
#pragma unroll
                for (int pr = 0; pr < 4; pr++) {
                    const int cb = pr & 1;
                    if (pr < 3) {
                        LDSM_X4(bfr[cb ^ 1][0], bfr[cb ^ 1][1],
                                bfr[cb ^ 1][2], bfr[cb ^ 1][3],
                                bRow + kboff + (pr + 1) * 16 * RSB * 2);
                    }
#pragma unroll
                    for (int mt = 0; mt < 2; mt++) {
                        mma_f16(acc[mt][2 * pr],     af[mt], bfr[cb][0], bfr[cb][1]);
                        mma_f16(acc[mt][2 * pr + 1], af[mt], bfr[cb][2], bfr[cb][3]);
                    }
                }
            }
            if (++slot == NSTG) slot = 0;
        }
        __syncthreads();   // protect slots before next segment's prologue

        // flush tile segment via atomicAdd
#pragma unroll
        for (int mt = 0; mt < 2; mt++) {
            int r = row0 + wm * 32 + mt * 16 + (lane >> 2);
#pragma unroll
            for (int nt = 0; nt < 8; nt++) {
                int cc = wn * 64 + nt * 8 + (lane & 3) * 2;
                atomicAdd(&g_Wh[(size_t)r * NT + cc],           acc[mt][nt][0]);
                atomicAdd(&g_Wh[(size_t)r * NT + cc + 1],       acc[mt][nt][1]);
                atomicAdd(&g_Wh[(size_t)(r + 8) * NT + cc],     acc[mt][nt][2]);
                atomicAdd(&g_Wh[(size_t)(r + 8) * NT + cc + 1], acc[mt][nt][3]);
            }
        }

        u += seg;
    }
#undef LDG_A
#undef STS_A
#undef ISSUE_B
}

// ---------------------------------------------------------------------------
// Kernel B: GAT attention + ELU. grid (256,4), 256 threads, 5 blocks/SM.
// ---------------------------------------------------------------------------
#define NP 52
__global__ __launch_bounds__(256, 5)
void attn_kernel(const float* __restrict__ a, float* __restrict__ out)
{
    __shared__ float sWh[NP][68];
    __shared__ float sA2[NP][68];
    __shared__ float sE[NP][NP];
    __shared__ float sS1[NN];
    __shared__ unsigned char sAdj[NN * NN];

    const int b    = blockIdx.x;
    const int h    = blockIdx.y;
    const int tid  = threadIdx.x;
    const int lane = tid & 31;
    const int wid  = tid >> 5;

    {
        const unsigned* src = (const unsigned*)(g_adj + (size_t)b * NN * NN);
        unsigned* dst = (unsigned*)sAdj;
        for (int i = tid; i < NN * NN / 4; i += 256) dst[i] = src[i];
    }

    if (tid < 2 * 68) {
        int r = 50 + tid / 68, cidx = tid % 68;
        sWh[r][cidx] = 0.f;
        sA2[r][cidx] = 0.f;
    }

    for (int idx = tid; idx < NN * OO / 4; idx += 256) {
        int n_ = idx >> 4;
        int o4 = (idx & 15) * 4;
        float4 w  = *(const float4*)&g_Wh[(size_t)(b * NN + n_) * NT + h * OO + o4];
        float4 av = *(const float4*)&a[(size_t)(h * NN + n_) * (2 * OO) + OO + o4];
        *(float4*)&sWh[n_][o4] = w;
        *(float4*)&sA2[n_][o4] = av;
    }
    __syncthreads();

    for (int n_ = wid; n_ < NN; n_ += 8) {
        float a1v0 = a[(size_t)(h * NN + n_) * (2 * OO) + lane];
        float a1v1 = a[(size_t)(h * NN + n_) * (2 * OO) + lane + 32];
        float v = sWh[n_][lane] * a1v0 + sWh[n_][lane + 32] * a1v1;
#pragma unroll
        for (int off = 16; off; off >>= 1) v += __shfl_xor_sync(0xffffffffu, v, off);
        if (lane == 0) sS1[n_] = v;
    }

    if (tid < 169) {
        const int n0 = (tid / 13) * 4;
        const int m0 = (tid % 13) * 4;
        float acc[4][4];
#pragma unroll
        for (int i = 0; i < 4; i++)
#pragma unroll
            for (int j = 0; j < 4; j++) acc[i][j] = 0.f;
#pragma unroll 8
        for (int o = 0; o < OO; o++) {
            float av[4], wv[4];
#pragma unroll
            for (int i = 0; i < 4; i++) av[i] = sA2[n0 + i][o];
#pragma unroll
            for (int j = 0; j < 4; j++) wv[j] = sWh[m0 + j][o];
#pragma unroll
            for (int i = 0; i < 4; i++)
#pragma unroll
                for (int j = 0; j < 4; j++)
                    acc[i][j] = fmaf(av[i], wv[j], acc[i][j]);
        }
#pragma unroll
        for (int i = 0; i < 4; i++)
#pragma unroll
            for (int j = 0; j < 4; j++) sE[n0 + i][m0 + j] = acc[i][j];
    }
    __syncthreads();

    for (int n_ = wid; n_ < NN; n_ += 8) {
        float s1v = sS1[n_];
        int m0 = lane, m1 = lane + 32;
        float t0 = s1v + sE[n_][m0];
        t0 = (t0 >= 0.f) ? t0 : 0.2f * t0;
        float v0 = sAdj[n_ * NN + m0] ? t0 : -9e15f;
        float v1 = -9e15f;
        if (m1 < NN) {
            float t1 = s1v + sE[n_][m1];
            t1 = (t1 >= 0.f) ? t1 : 0.2f * t1;
            v1 = sAdj[n_ * NN + m1] ? t1 : -9e15f;
        }
        float mx = fmaxf(v0, v1);
#pragma unroll
        for (int off = 16; off; off >>= 1)
            mx = fmaxf(mx, __shfl_xor_sync(0xffffffffu, mx, off));
        float e0_ = __expf(v0 - mx);
        float e1_ = (m1 < NN) ? __expf(v1 - mx) : 0.f;
        float sum = e0_ + e1_;
#pragma unroll
        for (int off = 16; off; off >>= 1)
            sum += __shfl_xor_sync(0xffffffffu, sum, off);
        float inv = 1.f / sum;
        sE[n_][m0] = e0_ * inv;
        if (m1 < NN) sE[n_][m1] = e1_ * inv;
    }
    __syncthreads();

    if (tid < 208) {
        const int n0 = (tid / 16) * 4;
        const int o4 = (tid % 16) * 4;
        float4 acc[4];
#pragma unroll
        for (int i = 0; i < 4; i++) acc[i] = make_float4(0.f, 0.f, 0.f, 0.f);
#pragma unroll 5
        for (int m = 0; m < NN; m++) {
            float4 wv = *(const float4*)&sWh[m][o4];
#pragma unroll
            for (int i = 0; i < 4; i++) {
                float at = sE[n0 + i][m];
                acc[i].x = fmaf(at, wv.x, acc[i].x);
                acc[i].y = fmaf(at, wv.y, acc[i].y);
                acc[i].z = fmaf(at, wv.z, acc[i].z);
                acc[i].w = fmaf(at, wv.w, acc[i].w);
            }
        }
#pragma unroll
        for (int i = 0; i < 4; i++) {
            int n_ = n0 + i;
            if (n_ < NN) {
                float4 wv = *(const float4*)&sWh[n_][o4];
                float4 v = make_float4(acc[i].x + 0.3f * wv.x,
                                       acc[i].y + 0.3f * wv.y,
                                       acc[i].z + 0.3f * wv.z,
                                       acc[i].w + 0.3f * wv.w);
                v.x = (v.x > 0.f) ? v.x : (__expf(v.x) - 1.f);
                v.y = (v.y > 0.f) ? v.y : (__expf(v.y) - 1.f);
                v.z = (v.z > 0.f) ? v.z : (__expf(v.z) - 1.f);
                v.w = (v.w > 0.f) ? v.w : (__expf(v.w) - 1.f);
                *(float4*)&out[(size_t)(b * NN + n_) * NT + h * OO + o4] = v;
            }
        }
    }
}

// ---------------------------------------------------------------------------
extern "C" void kernel_launch(void* const* d_in, const int* in_sizes, int n_in,
                              void* d_out, int out_size)
{
    const float* h_    = (const float*)d_in[0];  // (B, N, F)
    const float* probs = (const float*)d_in[1];  // (B, N*N)
    const float* u_    = (const float*)d_in[2];  // (B, N*N, 2)
    const float* W_    = (const float*)d_in[3];  // (H, F, O)
    const float* a_    = (const float*)d_in[4];  // (H, N, 2*O)
    float* out = (float*)d_out;

    zero_kernel<<<592, 256>>>();
    adj_kernel<<<(BB * NN * NN + 255) / 256, 256>>>(probs, u_);

    dim3 tgrid(FF / 32, HH);
    wT_kernel<<<tgrid, 256>>>(W_);

    cudaFuncSetAttribute(gemm_f16, cudaFuncAttributeMaxDynamicSharedMemorySize,
                         SMEM_BYTES);
    gemm_f16<<<GRID_G, NTHREADS, SMEM_BYTES>>>(h_);

    dim3 agrid(BB, HH);
    attn_kernel<<<agrid, 256>>>(a_, out);
}